// round 3
// baseline (speedup 1.0000x reference)
#include <cuda_runtime.h>
#include <cuda_bf16.h>
#include <math.h>

#define NB 4
#define NN 2048
#define PIN 256
#define POUT 128
#define FIN 512
#define FOUT 128
#define KH 32

typedef unsigned long long ull;

// ---------------- scratch (device globals) ----------------
__device__ float g_x [2][NB][NN][POUT];
__device__ float g_xh[2][NB][NN][POUT];
__device__ float g_s1[2][NB][NN][4];
__device__ float g_s2[2][NB][NN][4];
__device__ float g_G [2][NB][NN][POUT];
__device__ float g_h [2][NB][FOUT];
__device__ float g_gaga[2][NB][FOUT];

// ---------------- f32x2 helpers ----------------
__device__ __forceinline__ ull ffma2(ull a, ull b, ull c) {
    ull d; asm("fma.rn.f32x2 %0, %1, %2, %3;" : "=l"(d) : "l"(a), "l"(b), "l"(c)); return d;
}
__device__ __forceinline__ ull pack2(float v) {
    ull r; asm("mov.b64 %0, {%1, %1};" : "=l"(r) : "f"(v)); return r;
}
__device__ __forceinline__ ull packpair(float a, float b) {
    ull r; asm("mov.b64 %0, {%1, %2};" : "=l"(r) : "f"(a), "f"(b)); return r;
}
__device__ __forceinline__ float2 unpack2(ull v) {
    float2 r; asm("mov.b64 {%0, %1}, %2;" : "=f"(r.x), "=f"(r.y) : "l"(v)); return r;
}

// ---------------- GEMM: C[M,128] = A[M,KC] @ W[128,KC]^T + bias ----------------
template<int KC>
__device__ __forceinline__ void gemm_body(const float* __restrict__ A,
                                          const float* __restrict__ W,
                                          const float* __restrict__ bias,
                                          float* __restrict__ C)
{
    __shared__ float As[32][72];
    __shared__ float Ws[32][132];
    int t = threadIdx.x;
    int r0 = blockIdx.x * 64;
    int rr = (t >> 5) * 8;
    int cc = (t & 31) * 4;

    ull acc[4][4];
#pragma unroll
    for (int j = 0; j < 4; ++j)
#pragma unroll
        for (int c = 0; c < 4; ++c) acc[j][c] = 0ull;

    for (int kt = 0; kt < KC; kt += 32) {
        __syncthreads();
#pragma unroll
        for (int q = 0; q < 2; ++q) {
            int idx = t + 256 * q;
            int row = idx >> 3, kq = (idx & 7) * 4;
            float4 v = *reinterpret_cast<const float4*>(&A[(size_t)(r0 + row) * KC + kt + kq]);
            As[kq][row] = v.x; As[kq + 1][row] = v.y; As[kq + 2][row] = v.z; As[kq + 3][row] = v.w;
        }
#pragma unroll
        for (int q = 0; q < 4; ++q) {
            int idx = t + 256 * q;
            int c = idx >> 3, kq = (idx & 7) * 4;
            float4 v = *reinterpret_cast<const float4*>(&W[(size_t)c * KC + kt + kq]);
            Ws[kq][c] = v.x; Ws[kq + 1][c] = v.y; Ws[kq + 2][c] = v.z; Ws[kq + 3][c] = v.w;
        }
        __syncthreads();
#pragma unroll
        for (int k = 0; k < 32; ++k) {
            const ulonglong2* ap = reinterpret_cast<const ulonglong2*>(&As[k][rr]);
            ulonglong2 a01 = ap[0], a23 = ap[1];
            float4 w4 = *reinterpret_cast<const float4*>(&Ws[k][cc]);
            ull w0 = pack2(w4.x), w1 = pack2(w4.y), w2 = pack2(w4.z), w3 = pack2(w4.w);
            acc[0][0]=ffma2(a01.x,w0,acc[0][0]); acc[0][1]=ffma2(a01.x,w1,acc[0][1]);
            acc[0][2]=ffma2(a01.x,w2,acc[0][2]); acc[0][3]=ffma2(a01.x,w3,acc[0][3]);
            acc[1][0]=ffma2(a01.y,w0,acc[1][0]); acc[1][1]=ffma2(a01.y,w1,acc[1][1]);
            acc[1][2]=ffma2(a01.y,w2,acc[1][2]); acc[1][3]=ffma2(a01.y,w3,acc[1][3]);
            acc[2][0]=ffma2(a23.x,w0,acc[2][0]); acc[2][1]=ffma2(a23.x,w1,acc[2][1]);
            acc[2][2]=ffma2(a23.x,w2,acc[2][2]); acc[2][3]=ffma2(a23.x,w3,acc[2][3]);
            acc[3][0]=ffma2(a23.y,w0,acc[3][0]); acc[3][1]=ffma2(a23.y,w1,acc[3][1]);
            acc[3][2]=ffma2(a23.y,w2,acc[3][2]); acc[3][3]=ffma2(a23.y,w3,acc[3][3]);
        }
    }
    float b0=0.f,b1=0.f,b2=0.f,b3=0.f;
    if (bias) { b0=bias[cc]; b1=bias[cc+1]; b2=bias[cc+2]; b3=bias[cc+3]; }
#pragma unroll
    for (int j = 0; j < 4; ++j) {
        float2 v0=unpack2(acc[j][0]), v1=unpack2(acc[j][1]), v2=unpack2(acc[j][2]), v3=unpack2(acc[j][3]);
        int rowA = r0 + rr + j * 2;
        float4 oA = make_float4(v0.x+b0, v1.x+b1, v2.x+b2, v3.x+b3);
        float4 oB = make_float4(v0.y+b0, v1.y+b1, v2.y+b2, v3.y+b3);
        *reinterpret_cast<float4*>(&C[(size_t)rowA * 128 + cc]) = oA;
        *reinterpret_cast<float4*>(&C[(size_t)(rowA + 1) * 128 + cc]) = oB;
    }
}

__global__ __launch_bounds__(256)
void gemm_init_kernel(const float* __restrict__ bio_a, const float* __restrict__ bio_b,
                      const float* __restrict__ W, const float* __restrict__ bias)
{
    gemm_body<PIN>(blockIdx.z ? bio_b : bio_a, W, bias,
                   blockIdx.z ? &g_x[1][0][0][0] : &g_x[0][0][0][0]);
}
__global__ __launch_bounds__(256)
void gemm_proj_kernel(const float* __restrict__ W)
{
    gemm_body<POUT>(blockIdx.z ? &g_x[1][0][0][0] : &g_x[0][0][0][0], W, nullptr,
                    blockIdx.z ? &g_xh[1][0][0][0] : &g_xh[0][0][0][0]);
}

// ---------------- per-node attention scalars ----------------
__global__ void s_kernel(const float* __restrict__ attw)
{
    int g = blockIdx.x * blockDim.x + threadIdx.x;
    if (g >= 2 * NB * NN) return;
    int br = g / (NB * NN);
    int rem = g - br * NB * NN;
    int b = rem / NN, i = rem - b * NN;
    const float* xr = &g_xh[br][b][i][0];
    float s1o[4], s2o[4];
#pragma unroll
    for (int h = 0; h < 4; ++h) {
        float s1 = 0.f, s2 = 0.f;
#pragma unroll
        for (int k = 0; k < KH; k += 4) {
            float4 xv = *reinterpret_cast<const float4*>(&xr[h * KH + k]);
            float4 w1 = *reinterpret_cast<const float4*>(&attw[h * 64 + k]);
            float4 w2 = *reinterpret_cast<const float4*>(&attw[h * 64 + KH + k]);
            s1 += xv.x*w1.x + xv.y*w1.y + xv.z*w1.z + xv.w*w1.w;
            s2 += xv.x*w2.x + xv.y*w2.y + xv.z*w2.z + xv.w*w2.w;
        }
        s1o[h] = s1; s2o[h] = s2;
    }
    *reinterpret_cast<float4*>(&g_s1[br][b][i][0]) = make_float4(s1o[0],s1o[1],s1o[2],s1o[3]);
    *reinterpret_cast<float4*>(&g_s2[br][b][i][0]) = make_float4(s2o[0],s2o[1],s2o[2],s2o[3]);
}

// ---------------- fused GAT attention ----------------
#define BI 32
#define TJ 64
#define WS 68
#define ATTN_SMEM ((TJ * 128 + BI * 4 * WS) * 4)

__global__ __launch_bounds__(256)
void attn_kernel(const int* __restrict__ adjA, const int* __restrict__ adjB,
                 const float* __restrict__ attb)
{
    extern __shared__ float sm[];
    float* xh_s = sm;               // [TJ][128]
    float* w_s  = sm + TJ * 128;    // [BI*4][WS]

    int br = blockIdx.z, b = blockIdx.y;
    int i0 = blockIdx.x * BI;
    const int* adj = (br ? adjB : adjA) + (size_t)b * NN * NN;
    const float* xh = &g_xh[br][b][0][0];

    int t = threadIdx.x;
    int ib = t >> 4;
    int d0 = (t & 15) * 8;
    int h = d0 >> 5;
    int waBase = (ib * 4 + h) * WS;
    int wbBase = ((ib + 16) * 4 + h) * WS;

    float4 ab = *reinterpret_cast<const float4*>(attb);
    ull one2 = pack2(1.0f);
    ull A0=0,A1=0,A2=0,A3=0,B0=0,B1=0,B2=0,B3=0,accZ=0;

    for (int jt = 0; jt < NN / TJ; ++jt) {
        int j0 = jt * TJ;
        __syncthreads();
#pragma unroll
        for (int q = 0; q < 8; ++q) {
            int f = t + 256 * q;
            int row = f >> 5, c4 = (f & 31) << 2;
            *reinterpret_cast<float4*>(&xh_s[row * 128 + c4]) =
                *reinterpret_cast<const float4*>(&xh[(size_t)(j0 + row) * 128 + c4]);
        }
#pragma unroll
        for (int q = 0; q < 8; ++q) {
            int p = t + 256 * q;
            int i = p >> 6, jj = p & 63;
            int av = adj[(size_t)(i0 + i) * NN + j0 + jj];
            float w0=0.f,w1=0.f,w2=0.f,w3=0.f;
            if (av) {
                float4 s2v = *reinterpret_cast<const float4*>(&g_s2[br][b][j0 + jj][0]);
                float4 s1v = *reinterpret_cast<const float4*>(&g_s1[br][b][i0 + i][0]);
                float t0 = s1v.x+s2v.x+ab.x, t1 = s1v.y+s2v.y+ab.y;
                float t2 = s1v.z+s2v.z+ab.z, t3 = s1v.w+s2v.w+ab.w;
                w0 = __expf(t0 >= 0.f ? t0 : 0.2f*t0);
                w1 = __expf(t1 >= 0.f ? t1 : 0.2f*t1);
                w2 = __expf(t2 >= 0.f ? t2 : 0.2f*t2);
                w3 = __expf(t3 >= 0.f ? t3 : 0.2f*t3);
            }
            w_s[(i*4+0)*WS+jj]=w0; w_s[(i*4+1)*WS+jj]=w1;
            w_s[(i*4+2)*WS+jj]=w2; w_s[(i*4+3)*WS+jj]=w3;
        }
        __syncthreads();
#pragma unroll 4
        for (int jj = 0; jj < TJ; ++jj) {
            float wa = w_s[waBase + jj];
            float wb = w_s[wbBase + jj];
            ull wa2 = pack2(wa), wb2 = pack2(wb);
            const ulonglong2* xp = reinterpret_cast<const ulonglong2*>(&xh_s[jj * 128 + d0]);
            ulonglong2 xlo = xp[0], xhi = xp[1];
            A0 = ffma2(xlo.x, wa2, A0); A1 = ffma2(xlo.y, wa2, A1);
            A2 = ffma2(xhi.x, wa2, A2); A3 = ffma2(xhi.y, wa2, A3);
            B0 = ffma2(xlo.x, wb2, B0); B1 = ffma2(xlo.y, wb2, B1);
            B2 = ffma2(xhi.x, wb2, B2); B3 = ffma2(xhi.y, wb2, B3);
            accZ = ffma2(packpair(wa, wb), one2, accZ);
        }
    }

    float2 zz = unpack2(accZ);
#pragma unroll
    for (int half = 0; half < 2; ++half) {
        int row = i0 + ib + half * 16;
        float z = half ? zz.y : zz.x;
        float inv = 1.0f / ((z == 0.f) ? 1.f : z);
        float2 v0 = unpack2(half ? B0 : A0);
        float2 v1 = unpack2(half ? B1 : A1);
        float2 v2 = unpack2(half ? B2 : A2);
        float2 v3 = unpack2(half ? B3 : A3);
        float4 x0 = *reinterpret_cast<const float4*>(&g_x[br][b][row][d0]);
        float4 x1 = *reinterpret_cast<const float4*>(&g_x[br][b][row][d0 + 4]);
        float4 o0, o1;
        o0.x = fmaxf(v0.x*inv,0.f)+x0.x; o0.y = fmaxf(v0.y*inv,0.f)+x0.y;
        o0.z = fmaxf(v1.x*inv,0.f)+x0.z; o0.w = fmaxf(v1.y*inv,0.f)+x0.w;
        o1.x = fmaxf(v2.x*inv,0.f)+x1.x; o1.y = fmaxf(v2.y*inv,0.f)+x1.y;
        o1.z = fmaxf(v3.x*inv,0.f)+x1.z; o1.w = fmaxf(v3.y*inv,0.f)+x1.w;
        *reinterpret_cast<float4*>(&g_G[br][b][row][d0])     = o0;
        *reinterpret_cast<float4*>(&g_G[br][b][row][d0 + 4]) = o1;
    }
}

// ---------------- GGE MLP ----------------
__global__ __launch_bounds__(512)
void gge_kernel(const float* __restrict__ a_in, const float* __restrict__ b_in,
                const float* __restrict__ W1, const float* __restrict__ b1,
                const float* __restrict__ W2, const float* __restrict__ b2)
{
    int br = blockIdx.x;
    const float* in = br ? b_in : a_in;
    __shared__ float a_s[NB * FIN];
    __shared__ float h1_s[NB * 128];
    int t = threadIdx.x;
    for (int q = t; q < NB * FIN; q += 512) a_s[q] = in[q];
    __syncthreads();
    int bb = t >> 7, d = t & 127;
    float acc = b1[d];
    for (int k = 0; k < FIN; k += 4) {
        float4 w = *reinterpret_cast<const float4*>(&W1[(size_t)d * FIN + k]);
        acc += a_s[bb*FIN+k]*w.x + a_s[bb*FIN+k+1]*w.y + a_s[bb*FIN+k+2]*w.z + a_s[bb*FIN+k+3]*w.w;
    }
    h1_s[bb * 128 + d] = fmaxf(acc, 0.f);
    __syncthreads();
    float acc2 = b2[d];
    for (int k = 0; k < 128; k += 4) {
        float4 w = *reinterpret_cast<const float4*>(&W2[(size_t)d * 128 + k]);
        acc2 += h1_s[bb*128+k]*w.x + h1_s[bb*128+k+1]*w.y + h1_s[bb*128+k+2]*w.z + h1_s[bb*128+k+3]*w.w;
    }
    g_h[br][bb][d] = fmaxf(acc2, 0.f);
}

// ---------------- GAGA pooling ----------------
__global__ __launch_bounds__(256)
void gaga_kernel()
{
    int b = blockIdx.x, br = blockIdx.y;
    const float* G = &g_G[br][b][0][0];
    __shared__ float h_s[128];
    __shared__ float p_s[NN];
    __shared__ float redm[8], reds[8];
    __shared__ float partial[2][128];
    int t = threadIdx.x, lane = t & 31, w = t >> 5;

    if (t < 128) h_s[t] = g_h[br][b][t];
    __syncthreads();

    for (int n = w * 256; n < w * 256 + 256; ++n) {
        float4 gv = *reinterpret_cast<const float4*>(&G[(size_t)n * 128 + lane * 4]);
        float4 hv = *reinterpret_cast<const float4*>(&h_s[lane * 4]);
        float v = gv.x*hv.x + gv.y*hv.y + gv.z*hv.z + gv.w*hv.w;
#pragma unroll
        for (int s = 16; s > 0; s >>= 1) v += __shfl_xor_sync(0xffffffffu, v, s);
        if (lane == 0) p_s[n] = v;
    }
    __syncthreads();

    float m = -INFINITY;
    for (int n = t; n < NN; n += 256) m = fmaxf(m, p_s[n]);
#pragma unroll
    for (int s = 16; s > 0; s >>= 1) m = fmaxf(m, __shfl_xor_sync(0xffffffffu, m, s));
    if (lane == 0) redm[w] = m;
    __syncthreads();
    m = redm[0];
#pragma unroll
    for (int q = 1; q < 8; ++q) m = fmaxf(m, redm[q]);

    float s = 0.f;
    for (int n = t; n < NN; n += 256) { float e = __expf(p_s[n] - m); p_s[n] = e; s += e; }
#pragma unroll
    for (int q = 16; q > 0; q >>= 1) s += __shfl_xor_sync(0xffffffffu, s, q);
    if (lane == 0) reds[w] = s;
    __syncthreads();
    float Z = reds[0]+reds[1]+reds[2]+reds[3]+reds[4]+reds[5]+reds[6]+reds[7];

    int d = t & 127, half = t >> 7;
    float acc = 0.f;
    for (int n = half * 1024; n < half * 1024 + 1024; ++n)
        acc += p_s[n] * G[(size_t)n * 128 + d];
    partial[half][d] = acc;
    __syncthreads();
    if (t < 128) g_gaga[br][b][t] = (partial[0][t] + partial[1][t]) / Z;
}

// ---------------- LED head + log_softmax ----------------
__global__ __launch_bounds__(256)
void led_kernel(const float* __restrict__ convW, const float* __restrict__ convb,
                const float* __restrict__ W1, const float* __restrict__ b1,
                const float* __restrict__ W2, const float* __restrict__ b2,
                float* __restrict__ out)
{
    __shared__ float ea[NB * 256], eb[NB * 256];
    __shared__ float feat[NB * 512];
    __shared__ float x1[NB * 128];
    __shared__ float lg[NB * 2];
    int t = threadIdx.x;

    for (int q = t; q < NB * 256; q += 256) {
        int bb = q >> 8, d = q & 255;
        ea[q] = (d < 128) ? g_h[0][bb][d] : g_gaga[0][bb][d - 128];
        eb[q] = (d < 128) ? g_h[1][bb][d] : g_gaga[1][bb][d - 128];
    }
    __syncthreads();

    for (int q = t; q < NB * 256; q += 256) {
        int bb = q >> 8, o = q & 255;
        float sa = 0.f, sb = 0.f;
        for (int k = 0; k < 256; k += 4) {
            float4 w = *reinterpret_cast<const float4*>(&convW[(size_t)o * 256 + k]);
            sa += ea[bb*256+k]*w.x + ea[bb*256+k+1]*w.y + ea[bb*256+k+2]*w.z + ea[bb*256+k+3]*w.w;
            sb += eb[bb*256+k]*w.x + eb[bb*256+k+1]*w.y + eb[bb*256+k+2]*w.z + eb[bb*256+k+3]*w.w;
        }
        feat[bb * 512 + o]       = fmaxf(sa, sb) + convb[o];
        feat[bb * 512 + 256 + o] = ea[bb * 256 + o] - eb[bb * 256 + o];
    }
    __syncthreads();

    for (int q = t; q < NB * 128; q += 256) {
        int bb = q >> 7, d = q & 127;
        float acc = b1[d];
        for (int k = 0; k < 512; k += 4) {
            float4 w = *reinterpret_cast<const float4*>(&W1[(size_t)d * 512 + k]);
            acc += feat[bb*512+k]*w.x + feat[bb*512+k+1]*w.y + feat[bb*512+k+2]*w.z + feat[bb*512+k+3]*w.w;
        }
        x1[bb * 128 + d] = fmaxf(acc, 0.f);
    }
    __syncthreads();

    if (t < NB * 2) {
        int bb = t >> 1, c = t & 1;
        float acc = b2[c];
        for (int k = 0; k < 128; ++k) acc += x1[bb * 128 + k] * W2[c * 128 + k];
        lg[bb * 2 + c] = acc;
    }
    __syncthreads();
    if (t < NB) {
        float l0 = lg[t * 2], l1 = lg[t * 2 + 1];
        float m = fmaxf(l0, l1);
        float lse = m + logf(expf(l0 - m) + expf(l1 - m));
        out[t * 2]     = l0 - lse;
        out[t * 2 + 1] = l1 - lse;
    }
}

// ---------------- host ----------------
extern "C" void kernel_launch(void* const* d_in, const int* in_sizes, int n_in,
                              void* d_out, int out_size)
{
    const float* a      = (const float*)d_in[0];
    const float* bio_a  = (const float*)d_in[1];
    const int*   A      = (const int*)  d_in[2];
    const float* b      = (const float*)d_in[3];
    const float* bio_b  = (const float*)d_in[4];
    const int*   B      = (const int*)  d_in[5];
    const float* initW  = (const float*)d_in[6];
    const float* initb  = (const float*)d_in[7];
    const float* projW  = (const float*)d_in[8];
    const float* attw   = (const float*)d_in[9];
    const float* attb   = (const float*)d_in[10];
    const float* ggeW1  = (const float*)d_in[11];
    const float* ggeb1  = (const float*)d_in[12];
    const float* ggeW2  = (const float*)d_in[13];
    const float* ggeb2  = (const float*)d_in[14];
    const float* convW  = (const float*)d_in[15];
    const float* convb  = (const float*)d_in[16];
    const float* ledW1  = (const float*)d_in[17];
    const float* ledb1  = (const float*)d_in[18];
    const float* ledW2  = (const float*)d_in[19];
    const float* ledb2  = (const float*)d_in[20];
    float* out = (float*)d_out;

    cudaFuncSetAttribute(attn_kernel, cudaFuncAttributeMaxDynamicSharedMemorySize, ATTN_SMEM);

    dim3 gGemm(NB * NN / 64, 1, 2);
    gemm_init_kernel<<<gGemm, 256>>>(bio_a, bio_b, initW, initb);
    gemm_proj_kernel<<<gGemm, 256>>>(projW);
    s_kernel<<<(2 * NB * NN + 255) / 256, 256>>>(attw);
    gge_kernel<<<2, 512>>>(a, b, ggeW1, ggeb1, ggeW2, ggeb2);

    dim3 gAttn(NN / BI, NB, 2);
    attn_kernel<<<gAttn, 256, ATTN_SMEM>>>(A, B, attb);

    dim3 gGaga(NB, 2);
    gaga_kernel<<<gGaga, 256>>>();

    led_kernel<<<1, 256>>>(convW, convb, ledW1, ledb1, ledW2, ledb2, out);
}

// round 4
// speedup vs baseline: 1.1835x; 1.1835x over previous
#include <cuda_runtime.h>
#include <cuda_bf16.h>
#include <math.h>

#define NB 4
#define NN 2048
#define PIN 256
#define POUT 128
#define FIN 512
#define FOUT 128
#define KH 32

typedef unsigned long long ull;

// ---------------- scratch (device globals) ----------------
__device__ float g_x [2][NB][NN][POUT];
__device__ float g_xh[2][NB][NN][POUT];
__device__ float g_s1[2][NB][NN][4];
__device__ float g_s2[2][NB][NN][4];
__device__ float g_G [2][NB][NN][POUT];
__device__ float g_h [2][NB][FOUT];
__device__ float g_gaga[2][NB][FOUT];

// ---------------- f32x2 helpers ----------------
__device__ __forceinline__ ull ffma2(ull a, ull b, ull c) {
    ull d; asm("fma.rn.f32x2 %0, %1, %2, %3;" : "=l"(d) : "l"(a), "l"(b), "l"(c)); return d;
}
__device__ __forceinline__ ull pack2(float v) {
    ull r; asm("mov.b64 %0, {%1, %1};" : "=l"(r) : "f"(v)); return r;
}
__device__ __forceinline__ ull packpair(float a, float b) {
    ull r; asm("mov.b64 %0, {%1, %2};" : "=l"(r) : "f"(a), "f"(b)); return r;
}
__device__ __forceinline__ float2 unpack2(ull v) {
    float2 r; asm("mov.b64 {%0, %1}, %2;" : "=f"(r.x), "=f"(r.y) : "l"(v)); return r;
}

// ---------------- GEMM: C[M,128] = A[M,KC] @ W[128,KC]^T + bias ----------------
template<int KC>
__device__ __forceinline__ void gemm_body(const float* __restrict__ A,
                                          const float* __restrict__ W,
                                          const float* __restrict__ bias,
                                          float* __restrict__ C)
{
    __shared__ float As[32][72];
    __shared__ float Ws[32][132];
    int t = threadIdx.x;
    int r0 = blockIdx.x * 64;
    int rr = (t >> 5) * 8;
    int cc = (t & 31) * 4;

    ull acc[4][4];
#pragma unroll
    for (int j = 0; j < 4; ++j)
#pragma unroll
        for (int c = 0; c < 4; ++c) acc[j][c] = 0ull;

    for (int kt = 0; kt < KC; kt += 32) {
        __syncthreads();
#pragma unroll
        for (int q = 0; q < 2; ++q) {
            int idx = t + 256 * q;
            int row = idx >> 3, kq = (idx & 7) * 4;
            float4 v = *reinterpret_cast<const float4*>(&A[(size_t)(r0 + row) * KC + kt + kq]);
            As[kq][row] = v.x; As[kq + 1][row] = v.y; As[kq + 2][row] = v.z; As[kq + 3][row] = v.w;
        }
#pragma unroll
        for (int q = 0; q < 4; ++q) {
            int idx = t + 256 * q;
            int c = idx >> 3, kq = (idx & 7) * 4;
            float4 v = *reinterpret_cast<const float4*>(&W[(size_t)c * KC + kt + kq]);
            Ws[kq][c] = v.x; Ws[kq + 1][c] = v.y; Ws[kq + 2][c] = v.z; Ws[kq + 3][c] = v.w;
        }
        __syncthreads();
#pragma unroll
        for (int k = 0; k < 32; ++k) {
            const ulonglong2* ap = reinterpret_cast<const ulonglong2*>(&As[k][rr]);
            ulonglong2 a01 = ap[0], a23 = ap[1];
            float4 w4 = *reinterpret_cast<const float4*>(&Ws[k][cc]);
            ull w0 = pack2(w4.x), w1 = pack2(w4.y), w2 = pack2(w4.z), w3 = pack2(w4.w);
            acc[0][0]=ffma2(a01.x,w0,acc[0][0]); acc[0][1]=ffma2(a01.x,w1,acc[0][1]);
            acc[0][2]=ffma2(a01.x,w2,acc[0][2]); acc[0][3]=ffma2(a01.x,w3,acc[0][3]);
            acc[1][0]=ffma2(a01.y,w0,acc[1][0]); acc[1][1]=ffma2(a01.y,w1,acc[1][1]);
            acc[1][2]=ffma2(a01.y,w2,acc[1][2]); acc[1][3]=ffma2(a01.y,w3,acc[1][3]);
            acc[2][0]=ffma2(a23.x,w0,acc[2][0]); acc[2][1]=ffma2(a23.x,w1,acc[2][1]);
            acc[2][2]=ffma2(a23.x,w2,acc[2][2]); acc[2][3]=ffma2(a23.x,w3,acc[2][3]);
            acc[3][0]=ffma2(a23.y,w0,acc[3][0]); acc[3][1]=ffma2(a23.y,w1,acc[3][1]);
            acc[3][2]=ffma2(a23.y,w2,acc[3][2]); acc[3][3]=ffma2(a23.y,w3,acc[3][3]);
        }
    }
    float b0=0.f,b1=0.f,b2=0.f,b3=0.f;
    if (bias) { b0=bias[cc]; b1=bias[cc+1]; b2=bias[cc+2]; b3=bias[cc+3]; }
#pragma unroll
    for (int j = 0; j < 4; ++j) {
        float2 v0=unpack2(acc[j][0]), v1=unpack2(acc[j][1]), v2=unpack2(acc[j][2]), v3=unpack2(acc[j][3]);
        int rowA = r0 + rr + j * 2;
        float4 oA = make_float4(v0.x+b0, v1.x+b1, v2.x+b2, v3.x+b3);
        float4 oB = make_float4(v0.y+b0, v1.y+b1, v2.y+b2, v3.y+b3);
        *reinterpret_cast<float4*>(&C[(size_t)rowA * 128 + cc]) = oA;
        *reinterpret_cast<float4*>(&C[(size_t)(rowA + 1) * 128 + cc]) = oB;
    }
}

__global__ __launch_bounds__(256)
void gemm_init_kernel(const float* __restrict__ bio_a, const float* __restrict__ bio_b,
                      const float* __restrict__ W, const float* __restrict__ bias)
{
    gemm_body<PIN>(blockIdx.z ? bio_b : bio_a, W, bias,
                   blockIdx.z ? &g_x[1][0][0][0] : &g_x[0][0][0][0]);
}
__global__ __launch_bounds__(256)
void gemm_proj_kernel(const float* __restrict__ W)
{
    gemm_body<POUT>(blockIdx.z ? &g_x[1][0][0][0] : &g_x[0][0][0][0], W, nullptr,
                    blockIdx.z ? &g_xh[1][0][0][0] : &g_xh[0][0][0][0]);
}

// ---------------- per-node attention scalars ----------------
__global__ void s_kernel(const float* __restrict__ attw)
{
    int g = blockIdx.x * blockDim.x + threadIdx.x;
    if (g >= 2 * NB * NN) return;
    int br = g / (NB * NN);
    int rem = g - br * NB * NN;
    int b = rem / NN, i = rem - b * NN;
    const float* xr = &g_xh[br][b][i][0];
    float s1o[4], s2o[4];
#pragma unroll
    for (int h = 0; h < 4; ++h) {
        float s1 = 0.f, s2 = 0.f;
#pragma unroll
        for (int k = 0; k < KH; k += 4) {
            float4 xv = *reinterpret_cast<const float4*>(&xr[h * KH + k]);
            float4 w1 = *reinterpret_cast<const float4*>(&attw[h * 64 + k]);
            float4 w2 = *reinterpret_cast<const float4*>(&attw[h * 64 + KH + k]);
            s1 += xv.x*w1.x + xv.y*w1.y + xv.z*w1.z + xv.w*w1.w;
            s2 += xv.x*w2.x + xv.y*w2.y + xv.z*w2.z + xv.w*w2.w;
        }
        s1o[h] = s1; s2o[h] = s2;
    }
    *reinterpret_cast<float4*>(&g_s1[br][b][i][0]) = make_float4(s1o[0],s1o[1],s1o[2],s1o[3]);
    *reinterpret_cast<float4*>(&g_s2[br][b][i][0]) = make_float4(s2o[0],s2o[1],s2o[2],s2o[3]);
}

// ---------------- fused GAT attention ----------------
// xh_s rows are stored PERMUTED: low 4 floats of each 8-chunk in [0,64),
// high 4 floats in [64,128). Makes both inner-loop LDS.128 reads contiguous
// across lanes 0-15 (conflict-free) instead of 32B-strided (4-way conflict).
#define BI 32
#define TJ 64
#define WS 68
#define ATTN_SMEM ((TJ * 128 + BI * 4 * WS) * 4)

__global__ __launch_bounds__(256)
void attn_kernel(const int* __restrict__ adjA, const int* __restrict__ adjB,
                 const float* __restrict__ attb)
{
    extern __shared__ float sm[];
    float* xh_s = sm;               // [TJ][128] permuted
    float* w_s  = sm + TJ * 128;    // [BI*4][WS]

    int br = blockIdx.z, b = blockIdx.y;
    int i0 = blockIdx.x * BI;
    const int* adj = (br ? adjB : adjA) + (size_t)b * NN * NN;
    const float* xh = &g_xh[br][b][0][0];

    int t = threadIdx.x;
    int ib = t >> 4;
    int d0 = (t & 15) * 8;
    int h = d0 >> 5;
    int d0h = d0 >> 1;              // permuted low-half offset
    int waBase = (ib * 4 + h) * WS;
    int wbBase = ((ib + 16) * 4 + h) * WS;

    float4 ab = *reinterpret_cast<const float4*>(attb);
    ull one2 = pack2(1.0f);
    ull A0=0,A1=0,A2=0,A3=0,B0=0,B1=0,B2=0,B3=0,accZ=0;

    for (int jt = 0; jt < NN / TJ; ++jt) {
        int j0 = jt * TJ;
        __syncthreads();
        // load xh tile with permutation: lane l covers chunk=(l&15), half=(l>>4)
#pragma unroll
        for (int q = 0; q < 8; ++q) {
            int f = t + 256 * q;
            int row = f >> 5, l = f & 31;
            int chunk = l & 15, half = l >> 4;
            int srcc = chunk * 8 + half * 4;
            float4 v = *reinterpret_cast<const float4*>(&xh[(size_t)(j0 + row) * 128 + srcc]);
            *reinterpret_cast<float4*>(&xh_s[row * 128 + half * 64 + chunk * 4]) = v;
        }
#pragma unroll
        for (int q = 0; q < 8; ++q) {
            int p = t + 256 * q;
            int i = p >> 6, jj = p & 63;
            int av = adj[(size_t)(i0 + i) * NN + j0 + jj];
            float w0=0.f,w1=0.f,w2=0.f,w3=0.f;
            if (av) {
                float4 s2v = *reinterpret_cast<const float4*>(&g_s2[br][b][j0 + jj][0]);
                float4 s1v = *reinterpret_cast<const float4*>(&g_s1[br][b][i0 + i][0]);
                float t0 = s1v.x+s2v.x+ab.x, t1 = s1v.y+s2v.y+ab.y;
                float t2 = s1v.z+s2v.z+ab.z, t3 = s1v.w+s2v.w+ab.w;
                w0 = __expf(t0 >= 0.f ? t0 : 0.2f*t0);
                w1 = __expf(t1 >= 0.f ? t1 : 0.2f*t1);
                w2 = __expf(t2 >= 0.f ? t2 : 0.2f*t2);
                w3 = __expf(t3 >= 0.f ? t3 : 0.2f*t3);
            }
            w_s[(i*4+0)*WS+jj]=w0; w_s[(i*4+1)*WS+jj]=w1;
            w_s[(i*4+2)*WS+jj]=w2; w_s[(i*4+3)*WS+jj]=w3;
        }
        __syncthreads();
#pragma unroll 4
        for (int jj = 0; jj < TJ; ++jj) {
            float wa = w_s[waBase + jj];
            float wb = w_s[wbBase + jj];
            ull wa2 = pack2(wa), wb2 = pack2(wb);
            const float* xrow = &xh_s[jj * 128];
            ulonglong2 xlo = *reinterpret_cast<const ulonglong2*>(xrow + d0h);
            ulonglong2 xhi = *reinterpret_cast<const ulonglong2*>(xrow + 64 + d0h);
            A0 = ffma2(xlo.x, wa2, A0); A1 = ffma2(xlo.y, wa2, A1);
            A2 = ffma2(xhi.x, wa2, A2); A3 = ffma2(xhi.y, wa2, A3);
            B0 = ffma2(xlo.x, wb2, B0); B1 = ffma2(xlo.y, wb2, B1);
            B2 = ffma2(xhi.x, wb2, B2); B3 = ffma2(xhi.y, wb2, B3);
            accZ = ffma2(packpair(wa, wb), one2, accZ);
        }
    }

    float2 zz = unpack2(accZ);
#pragma unroll
    for (int half = 0; half < 2; ++half) {
        int row = i0 + ib + half * 16;
        float z = half ? zz.y : zz.x;
        float inv = 1.0f / ((z == 0.f) ? 1.f : z);
        float2 v0 = unpack2(half ? B0 : A0);
        float2 v1 = unpack2(half ? B1 : A1);
        float2 v2 = unpack2(half ? B2 : A2);
        float2 v3 = unpack2(half ? B3 : A3);
        float4 x0 = *reinterpret_cast<const float4*>(&g_x[br][b][row][d0]);
        float4 x1 = *reinterpret_cast<const float4*>(&g_x[br][b][row][d0 + 4]);
        float4 o0, o1;
        o0.x = fmaxf(v0.x*inv,0.f)+x0.x; o0.y = fmaxf(v0.y*inv,0.f)+x0.y;
        o0.z = fmaxf(v1.x*inv,0.f)+x0.z; o0.w = fmaxf(v1.y*inv,0.f)+x0.w;
        o1.x = fmaxf(v2.x*inv,0.f)+x1.x; o1.y = fmaxf(v2.y*inv,0.f)+x1.y;
        o1.z = fmaxf(v3.x*inv,0.f)+x1.z; o1.w = fmaxf(v3.y*inv,0.f)+x1.w;
        *reinterpret_cast<float4*>(&g_G[br][b][row][d0])     = o0;
        *reinterpret_cast<float4*>(&g_G[br][b][row][d0 + 4]) = o1;
    }
}

// ---------------- GGE MLP: one block per (branch,batch), k-split ----------------
__global__ __launch_bounds__(512)
void gge_kernel(const float* __restrict__ a_in, const float* __restrict__ b_in,
                const float* __restrict__ W1, const float* __restrict__ b1,
                const float* __restrict__ W2, const float* __restrict__ b2)
{
    int br = blockIdx.x, bb = blockIdx.y;
    const float* in = (br ? b_in : a_in) + (size_t)bb * FIN;
    __shared__ float a_s[FIN];
    __shared__ float part[4][128];
    __shared__ float h1[128];
    int t = threadIdx.x;
    if (t < FIN) a_s[t] = in[t];
    __syncthreads();
    int d = t & 127, g = t >> 7;
    float acc = 0.f;
    for (int k = g * 128; k < g * 128 + 128; k += 4) {
        float4 w = *reinterpret_cast<const float4*>(&W1[(size_t)d * FIN + k]);
        acc += a_s[k]*w.x + a_s[k+1]*w.y + a_s[k+2]*w.z + a_s[k+3]*w.w;
    }
    part[g][d] = acc;
    __syncthreads();
    if (t < 128) h1[t] = fmaxf(part[0][t]+part[1][t]+part[2][t]+part[3][t] + b1[t], 0.f);
    __syncthreads();
    float acc2 = 0.f;
    for (int k = g * 32; k < g * 32 + 32; k += 4) {
        float4 w = *reinterpret_cast<const float4*>(&W2[(size_t)d * 128 + k]);
        acc2 += h1[k]*w.x + h1[k+1]*w.y + h1[k+2]*w.z + h1[k+3]*w.w;
    }
    part[g][d] = acc2;
    __syncthreads();
    if (t < 128) g_h[br][bb][t] = fmaxf(part[0][t]+part[1][t]+part[2][t]+part[3][t] + b2[t], 0.f);
}

// ---------------- GAGA pooling (1024 threads) ----------------
__global__ __launch_bounds__(1024)
void gaga_kernel()
{
    int b = blockIdx.x, br = blockIdx.y;
    const float* G = &g_G[br][b][0][0];
    __shared__ float h_s[128];
    __shared__ float p_s[NN];
    __shared__ float red1[32], red2[32];
    __shared__ float partial[8][128];
    int t = threadIdx.x, lane = t & 31, w = t >> 5; // 32 warps

    if (t < 128) h_s[t] = g_h[br][b][t];
    __syncthreads();

    for (int n = w * 64; n < w * 64 + 64; ++n) {
        float4 gv = *reinterpret_cast<const float4*>(&G[(size_t)n * 128 + lane * 4]);
        float4 hv = *reinterpret_cast<const float4*>(&h_s[lane * 4]);
        float v = gv.x*hv.x + gv.y*hv.y + gv.z*hv.z + gv.w*hv.w;
#pragma unroll
        for (int s = 16; s > 0; s >>= 1) v += __shfl_xor_sync(0xffffffffu, v, s);
        if (lane == 0) p_s[n] = v;
    }
    __syncthreads();

    float m = fmaxf(p_s[t], p_s[t + 1024]);
#pragma unroll
    for (int s = 16; s > 0; s >>= 1) m = fmaxf(m, __shfl_xor_sync(0xffffffffu, m, s));
    if (lane == 0) red1[w] = m;
    __syncthreads();
    if (w == 0) {
        float mm = red1[lane];
#pragma unroll
        for (int s = 16; s > 0; s >>= 1) mm = fmaxf(mm, __shfl_xor_sync(0xffffffffu, mm, s));
        if (lane == 0) red1[0] = mm;
    }
    __syncthreads();
    m = red1[0];

    float e0 = __expf(p_s[t] - m);
    float e1 = __expf(p_s[t + 1024] - m);
    p_s[t] = e0; p_s[t + 1024] = e1;
    float s = e0 + e1;
#pragma unroll
    for (int q = 16; q > 0; q >>= 1) s += __shfl_xor_sync(0xffffffffu, s, q);
    if (lane == 0) red2[w] = s;
    __syncthreads();
    if (w == 0) {
        float ss = red2[lane];
#pragma unroll
        for (int q = 16; q > 0; q >>= 1) ss += __shfl_xor_sync(0xffffffffu, ss, q);
        if (lane == 0) red2[0] = ss;
    }
    __syncthreads();
    float Z = red2[0];

    int d = t & 127, g = t >> 7; // 8 groups x 256 rows
    float acc = 0.f;
    for (int n = g * 256; n < g * 256 + 256; ++n)
        acc += p_s[n] * G[(size_t)n * 128 + d];
    partial[g][d] = acc;
    __syncthreads();
    if (t < 128) {
        float tot = 0.f;
#pragma unroll
        for (int q = 0; q < 8; ++q) tot += partial[q][t];
        g_gaga[br][b][t] = tot / Z;
    }
}

// ---------------- LED head + log_softmax (1024 threads) ----------------
__global__ __launch_bounds__(1024)
void led_kernel(const float* __restrict__ convW, const float* __restrict__ convb,
                const float* __restrict__ W1, const float* __restrict__ b1,
                const float* __restrict__ W2, const float* __restrict__ b2,
                float* __restrict__ out)
{
    __shared__ float ea[NB * 256], eb[NB * 256];
    __shared__ float feat[NB * 512];
    __shared__ float part2[2][NB * 128];
    __shared__ float x1[NB * 128];
    __shared__ float lg[NB * 2];
    int t = threadIdx.x;

    {
        int bb = t >> 8, d = t & 255;
        ea[t] = (d < 128) ? g_h[0][bb][d] : g_gaga[0][bb][d - 128];
        eb[t] = (d < 128) ? g_h[1][bb][d] : g_gaga[1][bb][d - 128];
    }
    __syncthreads();

    {
        int bb = t >> 8, o = t & 255;
        float sa = 0.f, sb = 0.f;
        for (int k = 0; k < 256; k += 4) {
            float4 w = *reinterpret_cast<const float4*>(&convW[(size_t)o * 256 + k]);
            sa += ea[bb*256+k]*w.x + ea[bb*256+k+1]*w.y + ea[bb*256+k+2]*w.z + ea[bb*256+k+3]*w.w;
            sb += eb[bb*256+k]*w.x + eb[bb*256+k+1]*w.y + eb[bb*256+k+2]*w.z + eb[bb*256+k+3]*w.w;
        }
        feat[bb * 512 + o]       = fmaxf(sa, sb) + convb[o];
        feat[bb * 512 + 256 + o] = ea[bb * 256 + o] - eb[bb * 256 + o];
    }
    __syncthreads();

    {
        int g = t >> 9, idx = t & 511;
        int bb = idx >> 7, d = idx & 127;
        float acc = 0.f;
        for (int k = g * 256; k < g * 256 + 256; k += 4) {
            float4 w = *reinterpret_cast<const float4*>(&W1[(size_t)d * 512 + k]);
            acc += feat[bb*512+k]*w.x + feat[bb*512+k+1]*w.y + feat[bb*512+k+2]*w.z + feat[bb*512+k+3]*w.w;
        }
        part2[g][idx] = acc;
    }
    __syncthreads();
    if (t < 512) {
        int d = t & 127;
        x1[t] = fmaxf(part2[0][t] + part2[1][t] + b1[d], 0.f);
    }
    __syncthreads();

    if (t < NB * 2) {
        int bb = t >> 1, c = t & 1;
        float acc = b2[c];
        for (int k = 0; k < 128; ++k) acc += x1[bb * 128 + k] * W2[c * 128 + k];
        lg[bb * 2 + c] = acc;
    }
    __syncthreads();
    if (t < NB) {
        float l0 = lg[t * 2], l1 = lg[t * 2 + 1];
        float m = fmaxf(l0, l1);
        float lse = m + logf(expf(l0 - m) + expf(l1 - m));
        out[t * 2]     = l0 - lse;
        out[t * 2 + 1] = l1 - lse;
    }
}

// ---------------- host ----------------
extern "C" void kernel_launch(void* const* d_in, const int* in_sizes, int n_in,
                              void* d_out, int out_size)
{
    const float* a      = (const float*)d_in[0];
    const float* bio_a  = (const float*)d_in[1];
    const int*   A      = (const int*)  d_in[2];
    const float* b      = (const float*)d_in[3];
    const float* bio_b  = (const float*)d_in[4];
    const int*   B      = (const int*)  d_in[5];
    const float* initW  = (const float*)d_in[6];
    const float* initb  = (const float*)d_in[7];
    const float* projW  = (const float*)d_in[8];
    const float* attw   = (const float*)d_in[9];
    const float* attb   = (const float*)d_in[10];
    const float* ggeW1  = (const float*)d_in[11];
    const float* ggeb1  = (const float*)d_in[12];
    const float* ggeW2  = (const float*)d_in[13];
    const float* ggeb2  = (const float*)d_in[14];
    const float* convW  = (const float*)d_in[15];
    const float* convb  = (const float*)d_in[16];
    const float* ledW1  = (const float*)d_in[17];
    const float* ledb1  = (const float*)d_in[18];
    const float* ledW2  = (const float*)d_in[19];
    const float* ledb2  = (const float*)d_in[20];
    float* out = (float*)d_out;

    cudaFuncSetAttribute(attn_kernel, cudaFuncAttributeMaxDynamicSharedMemorySize, ATTN_SMEM);

    dim3 gGemm(NB * NN / 64, 1, 2);
    gemm_init_kernel<<<gGemm, 256>>>(bio_a, bio_b, initW, initb);
    gemm_proj_kernel<<<gGemm, 256>>>(projW);
    s_kernel<<<(2 * NB * NN + 255) / 256, 256>>>(attw);

    // attn placed 4th: lands in the ncu-profiled launch slot
    dim3 gAttn(NN / BI, NB, 2);
    attn_kernel<<<gAttn, 256, ATTN_SMEM>>>(A, B, attb);

    dim3 gGge(2, NB);
    gge_kernel<<<gGge, 512>>>(a, b, ggeW1, ggeb1, ggeW2, ggeb2);

    dim3 gGaga(NB, 2);
    gaga_kernel<<<gGaga, 1024>>>();

    led_kernel<<<1, 1024>>>(convW, convb, ledW1, ledb1, ledW2, ledb2, out);
}

// round 5
// speedup vs baseline: 1.7204x; 1.4536x over previous
#include <cuda_runtime.h>
#include <cuda_bf16.h>
#include <math.h>

#define NB 4
#define NN 2048
#define PIN 256
#define POUT 128
#define FIN 512
#define FOUT 128
#define KH 32

typedef unsigned long long ull;

// ---------------- scratch (device globals) ----------------
__device__ float g_x [2][NB][NN][POUT];
__device__ float g_xh[2][NB][NN][POUT];
__device__ float g_s1[2][NB][NN][4];
__device__ float g_s2[2][NB][NN][4];
__device__ float g_G [2][NB][NN][POUT];
__device__ float g_h [2][NB][FOUT];
__device__ float g_gaga[2][NB][FOUT];

// ---------------- f32x2 helpers ----------------
__device__ __forceinline__ ull ffma2(ull a, ull b, ull c) {
    ull d; asm("fma.rn.f32x2 %0, %1, %2, %3;" : "=l"(d) : "l"(a), "l"(b), "l"(c)); return d;
}
__device__ __forceinline__ ull pack2(float v) {
    ull r; asm("mov.b64 %0, {%1, %1};" : "=l"(r) : "f"(v)); return r;
}
__device__ __forceinline__ ull packpair(float a, float b) {
    ull r; asm("mov.b64 %0, {%1, %2};" : "=l"(r) : "f"(a), "f"(b)); return r;
}
__device__ __forceinline__ float2 unpack2(ull v) {
    float2 r; asm("mov.b64 {%0, %1}, %2;" : "=f"(r.x), "=f"(r.y) : "l"(v)); return r;
}

// ---------------- GEMM: C[M,128] = A[M,KC] @ W[128,KC]^T + bias ----------------
template<int KC>
__device__ __forceinline__ void gemm_body(const float* __restrict__ A,
                                          const float* __restrict__ W,
                                          const float* __restrict__ bias,
                                          float* __restrict__ C)
{
    __shared__ float As[32][72];
    __shared__ float Ws[32][132];
    int t = threadIdx.x;
    int r0 = blockIdx.x * 64;
    int rr = (t >> 5) * 8;
    int cc = (t & 31) * 4;

    ull acc[4][4];
#pragma unroll
    for (int j = 0; j < 4; ++j)
#pragma unroll
        for (int c = 0; c < 4; ++c) acc[j][c] = 0ull;

    for (int kt = 0; kt < KC; kt += 32) {
        __syncthreads();
#pragma unroll
        for (int q = 0; q < 2; ++q) {
            int idx = t + 256 * q;
            int row = idx >> 3, kq = (idx & 7) * 4;
            float4 v = *reinterpret_cast<const float4*>(&A[(size_t)(r0 + row) * KC + kt + kq]);
            As[kq][row] = v.x; As[kq + 1][row] = v.y; As[kq + 2][row] = v.z; As[kq + 3][row] = v.w;
        }
#pragma unroll
        for (int q = 0; q < 4; ++q) {
            int idx = t + 256 * q;
            int c = idx >> 3, kq = (idx & 7) * 4;
            float4 v = *reinterpret_cast<const float4*>(&W[(size_t)c * KC + kt + kq]);
            Ws[kq][c] = v.x; Ws[kq + 1][c] = v.y; Ws[kq + 2][c] = v.z; Ws[kq + 3][c] = v.w;
        }
        __syncthreads();
#pragma unroll
        for (int k = 0; k < 32; ++k) {
            const ulonglong2* ap = reinterpret_cast<const ulonglong2*>(&As[k][rr]);
            ulonglong2 a01 = ap[0], a23 = ap[1];
            float4 w4 = *reinterpret_cast<const float4*>(&Ws[k][cc]);
            ull w0 = pack2(w4.x), w1 = pack2(w4.y), w2 = pack2(w4.z), w3 = pack2(w4.w);
            acc[0][0]=ffma2(a01.x,w0,acc[0][0]); acc[0][1]=ffma2(a01.x,w1,acc[0][1]);
            acc[0][2]=ffma2(a01.x,w2,acc[0][2]); acc[0][3]=ffma2(a01.x,w3,acc[0][3]);
            acc[1][0]=ffma2(a01.y,w0,acc[1][0]); acc[1][1]=ffma2(a01.y,w1,acc[1][1]);
            acc[1][2]=ffma2(a01.y,w2,acc[1][2]); acc[1][3]=ffma2(a01.y,w3,acc[1][3]);
            acc[2][0]=ffma2(a23.x,w0,acc[2][0]); acc[2][1]=ffma2(a23.x,w1,acc[2][1]);
            acc[2][2]=ffma2(a23.x,w2,acc[2][2]); acc[2][3]=ffma2(a23.x,w3,acc[2][3]);
            acc[3][0]=ffma2(a23.y,w0,acc[3][0]); acc[3][1]=ffma2(a23.y,w1,acc[3][1]);
            acc[3][2]=ffma2(a23.y,w2,acc[3][2]); acc[3][3]=ffma2(a23.y,w3,acc[3][3]);
        }
    }
    float b0=0.f,b1=0.f,b2=0.f,b3=0.f;
    if (bias) { b0=bias[cc]; b1=bias[cc+1]; b2=bias[cc+2]; b3=bias[cc+3]; }
#pragma unroll
    for (int j = 0; j < 4; ++j) {
        float2 v0=unpack2(acc[j][0]), v1=unpack2(acc[j][1]), v2=unpack2(acc[j][2]), v3=unpack2(acc[j][3]);
        int rowA = r0 + rr + j * 2;
        float4 oA = make_float4(v0.x+b0, v1.x+b1, v2.x+b2, v3.x+b3);
        float4 oB = make_float4(v0.y+b0, v1.y+b1, v2.y+b2, v3.y+b3);
        *reinterpret_cast<float4*>(&C[(size_t)rowA * 128 + cc]) = oA;
        *reinterpret_cast<float4*>(&C[(size_t)(rowA + 1) * 128 + cc]) = oB;
    }
}

__global__ __launch_bounds__(256)
void gemm_init_kernel(const float* __restrict__ bio_a, const float* __restrict__ bio_b,
                      const float* __restrict__ W, const float* __restrict__ bias)
{
    gemm_body<PIN>(blockIdx.z ? bio_b : bio_a, W, bias,
                   blockIdx.z ? &g_x[1][0][0][0] : &g_x[0][0][0][0]);
}
__global__ __launch_bounds__(256)
void gemm_proj_kernel(const float* __restrict__ W)
{
    gemm_body<POUT>(blockIdx.z ? &g_x[1][0][0][0] : &g_x[0][0][0][0], W, nullptr,
                    blockIdx.z ? &g_xh[1][0][0][0] : &g_xh[0][0][0][0]);
}

// ---------------- per-node attention scalars ----------------
__global__ void s_kernel(const float* __restrict__ attw)
{
    int g = blockIdx.x * blockDim.x + threadIdx.x;
    if (g >= 2 * NB * NN) return;
    int br = g / (NB * NN);
    int rem = g - br * NB * NN;
    int b = rem / NN, i = rem - b * NN;
    const float* xr = &g_xh[br][b][i][0];
    float s1o[4], s2o[4];
#pragma unroll
    for (int h = 0; h < 4; ++h) {
        float s1 = 0.f, s2 = 0.f;
#pragma unroll
        for (int k = 0; k < KH; k += 4) {
            float4 xv = *reinterpret_cast<const float4*>(&xr[h * KH + k]);
            float4 w1 = *reinterpret_cast<const float4*>(&attw[h * 64 + k]);
            float4 w2 = *reinterpret_cast<const float4*>(&attw[h * 64 + KH + k]);
            s1 += xv.x*w1.x + xv.y*w1.y + xv.z*w1.z + xv.w*w1.w;
            s2 += xv.x*w2.x + xv.y*w2.y + xv.z*w2.z + xv.w*w2.w;
        }
        s1o[h] = s1; s2o[h] = s2;
    }
    *reinterpret_cast<float4*>(&g_s1[br][b][i][0]) = make_float4(s1o[0],s1o[1],s1o[2],s1o[3]);
    *reinterpret_cast<float4*>(&g_s2[br][b][i][0]) = make_float4(s2o[0],s2o[1],s2o[2],s2o[3]);
}

// ---------------- fused GAT attention (BI=64, 4 rows/thread) ----------------
// smem layout (floats):
//   xh_s  [0, 8192)            : TJ=64 rows x 128, half-permuted per row
//   w_s   [8192, 8192+18432)   : per jj (stride 288): [h*72 + i], i=row 0..63
//   adjbits (after w_s)        : 64 rows x 2 uint32 bitmask
#define BI 64
#define TJ 64
#define WJJ 288
#define WH  72
#define SM_W 8192
#define SM_ADJ (SM_W + TJ * WJJ)
#define ATTN_SMEM ((SM_ADJ) * 4 + BI * 2 * 4)

__global__ __launch_bounds__(256)
void attn_kernel(const int* __restrict__ adjA, const int* __restrict__ adjB,
                 const float* __restrict__ attb)
{
    extern __shared__ float sm[];
    float* xh_s = sm;
    float* w_s  = sm + SM_W;
    unsigned* adjbits = reinterpret_cast<unsigned*>(sm + SM_ADJ);

    int br = blockIdx.z, b = blockIdx.y;
    int i0 = blockIdx.x * BI;
    const int* adj = (br ? adjB : adjA) + (size_t)b * NN * NN;
    const float* xh = &g_xh[br][b][0][0];

    int t = threadIdx.x;
    int lane = t & 31, w = t >> 5;

    // phase-1 (exp fill) mapping: fixed row per thread, jj sweeps
    int p1_i = lane + 32 * (w & 1);
    int p1_jjb = w >> 1;                 // jj = p1_jjb + 4*q
    float4 ab  = *reinterpret_cast<const float4*>(attb);
    float4 s1v = *reinterpret_cast<const float4*>(&g_s1[br][b][i0 + p1_i][0]);
    s1v.x += ab.x; s1v.y += ab.y; s1v.z += ab.z; s1v.w += ab.w;

    // phase-2 (accumulate) mapping
    int ib  = t >> 4;                    // 0..15 -> rows 4ib..4ib+3
    int d0  = (t & 15) * 8;
    int h   = (t & 15) >> 2;
    int d0h = (t & 15) * 4;

    ull one2 = pack2(1.0f);
    ull acc[16];
#pragma unroll
    for (int q = 0; q < 16; ++q) acc[q] = 0ull;
    ull z01 = 0ull, z23 = 0ull;

    for (int jt = 0; jt < NN / TJ; ++jt) {
        int j0 = jt * TJ;
        __syncthreads();
        // xh tile (half-permuted rows)
#pragma unroll
        for (int q = 0; q < 8; ++q) {
            int f = t + 256 * q;
            int row = f >> 5, l = f & 31;
            int chunk = l & 15, half = l >> 4;
            float4 v = *reinterpret_cast<const float4*>(&xh[(size_t)(j0 + row) * 128 + chunk * 8 + half * 4]);
            *reinterpret_cast<float4*>(&xh_s[row * 128 + half * 64 + chunk * 4]) = v;
        }
        // adjacency -> bitmask (coalesced loads + ballot)
#pragma unroll
        for (int r = 0; r < 16; ++r) {
            int tau = w * 16 + r;
            int i = tau >> 1, grp = tau & 1;
            int av = adj[(size_t)(i0 + i) * NN + j0 + grp * 32 + lane];
            unsigned m = __ballot_sync(0xffffffffu, av != 0);
            if (lane == 0) adjbits[i * 2 + grp] = m;
        }
        __syncthreads();
        // exp fill: thread covers (p1_i, jj=p1_jjb+4q)
#pragma unroll 4
        for (int q = 0; q < 16; ++q) {
            int jj = p1_jjb + 4 * q;
            unsigned bit = (adjbits[p1_i * 2 + (jj >> 5)] >> (jj & 31)) & 1u;
            float w0 = 0.f, w1 = 0.f, w2 = 0.f, w3 = 0.f;
            if (bit) {
                float4 s2v = *reinterpret_cast<const float4*>(&g_s2[br][b][j0 + jj][0]);
                float t0 = s1v.x + s2v.x, t1 = s1v.y + s2v.y;
                float t2 = s1v.z + s2v.z, t3 = s1v.w + s2v.w;
                w0 = __expf(t0 >= 0.f ? t0 : 0.2f * t0);
                w1 = __expf(t1 >= 0.f ? t1 : 0.2f * t1);
                w2 = __expf(t2 >= 0.f ? t2 : 0.2f * t2);
                w3 = __expf(t3 >= 0.f ? t3 : 0.2f * t3);
            }
            float* wr = &w_s[jj * WJJ + p1_i];
            wr[0*WH] = w0; wr[1*WH] = w1; wr[2*WH] = w2; wr[3*WH] = w3;
        }
        __syncthreads();
        // main accumulate
#pragma unroll 2
        for (int jj = 0; jj < TJ; ++jj) {
            float4 wq = *reinterpret_cast<const float4*>(&w_s[jj * WJJ + h * WH + ib * 4]);
            const float* xrow = &xh_s[jj * 128];
            ulonglong2 xlo = *reinterpret_cast<const ulonglong2*>(xrow + d0h);
            ulonglong2 xhi = *reinterpret_cast<const ulonglong2*>(xrow + 64 + d0h);
            ull wp0 = pack2(wq.x), wp1 = pack2(wq.y), wp2 = pack2(wq.z), wp3 = pack2(wq.w);
            acc[0]  = ffma2(xlo.x, wp0, acc[0]);  acc[1]  = ffma2(xlo.y, wp0, acc[1]);
            acc[2]  = ffma2(xhi.x, wp0, acc[2]);  acc[3]  = ffma2(xhi.y, wp0, acc[3]);
            acc[4]  = ffma2(xlo.x, wp1, acc[4]);  acc[5]  = ffma2(xlo.y, wp1, acc[5]);
            acc[6]  = ffma2(xhi.x, wp1, acc[6]);  acc[7]  = ffma2(xhi.y, wp1, acc[7]);
            acc[8]  = ffma2(xlo.x, wp2, acc[8]);  acc[9]  = ffma2(xlo.y, wp2, acc[9]);
            acc[10] = ffma2(xhi.x, wp2, acc[10]); acc[11] = ffma2(xhi.y, wp2, acc[11]);
            acc[12] = ffma2(xlo.x, wp3, acc[12]); acc[13] = ffma2(xlo.y, wp3, acc[13]);
            acc[14] = ffma2(xhi.x, wp3, acc[14]); acc[15] = ffma2(xhi.y, wp3, acc[15]);
            z01 = ffma2(packpair(wq.x, wq.y), one2, z01);
            z23 = ffma2(packpair(wq.z, wq.w), one2, z23);
        }
    }

    float2 za = unpack2(z01), zb = unpack2(z23);
    float zs[4] = { za.x, za.y, zb.x, zb.y };
#pragma unroll
    for (int r = 0; r < 4; ++r) {
        int row = i0 + ib * 4 + r;
        float z = zs[r];
        float inv = 1.0f / ((z == 0.f) ? 1.f : z);
        float2 v0 = unpack2(acc[r*4+0]);
        float2 v1 = unpack2(acc[r*4+1]);
        float2 v2 = unpack2(acc[r*4+2]);
        float2 v3 = unpack2(acc[r*4+3]);
        float4 x0 = *reinterpret_cast<const float4*>(&g_x[br][b][row][d0]);
        float4 x1 = *reinterpret_cast<const float4*>(&g_x[br][b][row][d0 + 4]);
        float4 o0, o1;
        o0.x = fmaxf(v0.x*inv,0.f)+x0.x; o0.y = fmaxf(v0.y*inv,0.f)+x0.y;
        o0.z = fmaxf(v1.x*inv,0.f)+x0.z; o0.w = fmaxf(v1.y*inv,0.f)+x0.w;
        o1.x = fmaxf(v2.x*inv,0.f)+x1.x; o1.y = fmaxf(v2.y*inv,0.f)+x1.y;
        o1.z = fmaxf(v3.x*inv,0.f)+x1.z; o1.w = fmaxf(v3.y*inv,0.f)+x1.w;
        *reinterpret_cast<float4*>(&g_G[br][b][row][d0])     = o0;
        *reinterpret_cast<float4*>(&g_G[br][b][row][d0 + 4]) = o1;
    }
}

// ---------------- GGE MLP: one block per (branch,batch), k-split ----------------
__global__ __launch_bounds__(512)
void gge_kernel(const float* __restrict__ a_in, const float* __restrict__ b_in,
                const float* __restrict__ W1, const float* __restrict__ b1,
                const float* __restrict__ W2, const float* __restrict__ b2)
{
    int br = blockIdx.x, bb = blockIdx.y;
    const float* in = (br ? b_in : a_in) + (size_t)bb * FIN;
    __shared__ float a_s[FIN];
    __shared__ float part[4][128];
    __shared__ float h1[128];
    int t = threadIdx.x;
    if (t < FIN) a_s[t] = in[t];
    __syncthreads();
    int d = t & 127, g = t >> 7;
    float acc = 0.f;
    for (int k = g * 128; k < g * 128 + 128; k += 4) {
        float4 w = *reinterpret_cast<const float4*>(&W1[(size_t)d * FIN + k]);
        acc += a_s[k]*w.x + a_s[k+1]*w.y + a_s[k+2]*w.z + a_s[k+3]*w.w;
    }
    part[g][d] = acc;
    __syncthreads();
    if (t < 128) h1[t] = fmaxf(part[0][t]+part[1][t]+part[2][t]+part[3][t] + b1[t], 0.f);
    __syncthreads();
    float acc2 = 0.f;
    for (int k = g * 32; k < g * 32 + 32; k += 4) {
        float4 w = *reinterpret_cast<const float4*>(&W2[(size_t)d * 128 + k]);
        acc2 += h1[k]*w.x + h1[k+1]*w.y + h1[k+2]*w.z + h1[k+3]*w.w;
    }
    part[g][d] = acc2;
    __syncthreads();
    if (t < 128) g_h[br][bb][t] = fmaxf(part[0][t]+part[1][t]+part[2][t]+part[3][t] + b2[t], 0.f);
}

// ---------------- GAGA pooling (1024 threads) ----------------
__global__ __launch_bounds__(1024)
void gaga_kernel()
{
    int b = blockIdx.x, br = blockIdx.y;
    const float* G = &g_G[br][b][0][0];
    __shared__ float h_s[128];
    __shared__ float p_s[NN];
    __shared__ float red1[32], red2[32];
    __shared__ float partial[8][128];
    int t = threadIdx.x, lane = t & 31, w = t >> 5;

    if (t < 128) h_s[t] = g_h[br][b][t];
    __syncthreads();

    for (int n = w * 64; n < w * 64 + 64; ++n) {
        float4 gv = *reinterpret_cast<const float4*>(&G[(size_t)n * 128 + lane * 4]);
        float4 hv = *reinterpret_cast<const float4*>(&h_s[lane * 4]);
        float v = gv.x*hv.x + gv.y*hv.y + gv.z*hv.z + gv.w*hv.w;
#pragma unroll
        for (int s = 16; s > 0; s >>= 1) v += __shfl_xor_sync(0xffffffffu, v, s);
        if (lane == 0) p_s[n] = v;
    }
    __syncthreads();

    float m = fmaxf(p_s[t], p_s[t + 1024]);
#pragma unroll
    for (int s = 16; s > 0; s >>= 1) m = fmaxf(m, __shfl_xor_sync(0xffffffffu, m, s));
    if (lane == 0) red1[w] = m;
    __syncthreads();
    if (w == 0) {
        float mm = red1[lane];
#pragma unroll
        for (int s = 16; s > 0; s >>= 1) mm = fmaxf(mm, __shfl_xor_sync(0xffffffffu, mm, s));
        if (lane == 0) red1[0] = mm;
    }
    __syncthreads();
    m = red1[0];

    float e0 = __expf(p_s[t] - m);
    float e1 = __expf(p_s[t + 1024] - m);
    p_s[t] = e0; p_s[t + 1024] = e1;
    float s = e0 + e1;
#pragma unroll
    for (int q = 16; q > 0; q >>= 1) s += __shfl_xor_sync(0xffffffffu, s, q);
    if (lane == 0) red2[w] = s;
    __syncthreads();
    if (w == 0) {
        float ss = red2[lane];
#pragma unroll
        for (int q = 16; q > 0; q >>= 1) ss += __shfl_xor_sync(0xffffffffu, ss, q);
        if (lane == 0) red2[0] = ss;
    }
    __syncthreads();
    float Z = red2[0];

    int d = t & 127, g = t >> 7;
    float acc = 0.f;
    for (int n = g * 256; n < g * 256 + 256; ++n)
        acc += p_s[n] * G[(size_t)n * 128 + d];
    partial[g][d] = acc;
    __syncthreads();
    if (t < 128) {
        float tot = 0.f;
#pragma unroll
        for (int q = 0; q < 8; ++q) tot += partial[q][t];
        g_gaga[br][b][t] = tot / Z;
    }
}

// ---------------- LED head + log_softmax (1024 threads) ----------------
__global__ __launch_bounds__(1024)
void led_kernel(const float* __restrict__ convW, const float* __restrict__ convb,
                const float* __restrict__ W1, const float* __restrict__ b1,
                const float* __restrict__ W2, const float* __restrict__ b2,
                float* __restrict__ out)
{
    __shared__ float ea[NB * 256], eb[NB * 256];
    __shared__ float feat[NB * 512];
    __shared__ float part2[2][NB * 128];
    __shared__ float x1[NB * 128];
    __shared__ float lg[NB * 2];
    int t = threadIdx.x;

    {
        int bb = t >> 8, d = t & 255;
        ea[t] = (d < 128) ? g_h[0][bb][d] : g_gaga[0][bb][d - 128];
        eb[t] = (d < 128) ? g_h[1][bb][d] : g_gaga[1][bb][d - 128];
    }
    __syncthreads();

    {
        int bb = t >> 8, o = t & 255;
        float sa = 0.f, sb = 0.f;
        for (int k = 0; k < 256; k += 4) {
            float4 w = *reinterpret_cast<const float4*>(&convW[(size_t)o * 256 + k]);
            sa += ea[bb*256+k]*w.x + ea[bb*256+k+1]*w.y + ea[bb*256+k+2]*w.z + ea[bb*256+k+3]*w.w;
            sb += eb[bb*256+k]*w.x + eb[bb*256+k+1]*w.y + eb[bb*256+k+2]*w.z + eb[bb*256+k+3]*w.w;
        }
        feat[bb * 512 + o]       = fmaxf(sa, sb) + convb[o];
        feat[bb * 512 + 256 + o] = ea[bb * 256 + o] - eb[bb * 256 + o];
    }
    __syncthreads();

    {
        int g = t >> 9, idx = t & 511;
        int bb = idx >> 7, d = idx & 127;
        float acc = 0.f;
        for (int k = g * 256; k < g * 256 + 256; k += 4) {
            float4 w = *reinterpret_cast<const float4*>(&W1[(size_t)d * 512 + k]);
            acc += feat[bb*512+k]*w.x + feat[bb*512+k+1]*w.y + feat[bb*512+k+2]*w.z + feat[bb*512+k+3]*w.w;
        }
        part2[g][idx] = acc;
    }
    __syncthreads();
    if (t < 512) {
        int d = t & 127;
        x1[t] = fmaxf(part2[0][t] + part2[1][t] + b1[d], 0.f);
    }
    __syncthreads();

    if (t < NB * 2) {
        int bb = t >> 1, c = t & 1;
        float acc = b2[c];
        for (int k = 0; k < 128; ++k) acc += x1[bb * 128 + k] * W2[c * 128 + k];
        lg[bb * 2 + c] = acc;
    }
    __syncthreads();
    if (t < NB) {
        float l0 = lg[t * 2], l1 = lg[t * 2 + 1];
        float m = fmaxf(l0, l1);
        float lse = m + logf(expf(l0 - m) + expf(l1 - m));
        out[t * 2]     = l0 - lse;
        out[t * 2 + 1] = l1 - lse;
    }
}

// ---------------- host ----------------
extern "C" void kernel_launch(void* const* d_in, const int* in_sizes, int n_in,
                              void* d_out, int out_size)
{
    const float* a      = (const float*)d_in[0];
    const float* bio_a  = (const float*)d_in[1];
    const int*   A      = (const int*)  d_in[2];
    const float* b      = (const float*)d_in[3];
    const float* bio_b  = (const float*)d_in[4];
    const int*   B      = (const int*)  d_in[5];
    const float* initW  = (const float*)d_in[6];
    const float* initb  = (const float*)d_in[7];
    const float* projW  = (const float*)d_in[8];
    const float* attw   = (const float*)d_in[9];
    const float* attb   = (const float*)d_in[10];
    const float* ggeW1  = (const float*)d_in[11];
    const float* ggeb1  = (const float*)d_in[12];
    const float* ggeW2  = (const float*)d_in[13];
    const float* ggeb2  = (const float*)d_in[14];
    const float* convW  = (const float*)d_in[15];
    const float* convb  = (const float*)d_in[16];
    const float* ledW1  = (const float*)d_in[17];
    const float* ledb1  = (const float*)d_in[18];
    const float* ledW2  = (const float*)d_in[19];
    const float* ledb2  = (const float*)d_in[20];
    float* out = (float*)d_out;

    cudaFuncSetAttribute(attn_kernel, cudaFuncAttributeMaxDynamicSharedMemorySize, ATTN_SMEM);

    dim3 gGemm(NB * NN / 64, 1, 2);
    gemm_init_kernel<<<gGemm, 256>>>(bio_a, bio_b, initW, initb);
    gemm_proj_kernel<<<gGemm, 256>>>(projW);
    s_kernel<<<(2 * NB * NN + 255) / 256, 256>>>(attw);

    dim3 gAttn(NN / BI, NB, 2);
    attn_kernel<<<gAttn, 256, ATTN_SMEM>>>(A, B, attb);

    dim3 gGge(2, NB);
    gge_kernel<<<gGge, 512>>>(a, b, ggeW1, ggeb1, ggeW2, ggeb2);

    dim3 gGaga(NB, 2);
    gaga_kernel<<<gGaga, 1024>>>();

    led_kernel<<<1, 1024>>>(convW, convb, ledW1, ledb1, ledW2, ledb2, out);
}

// round 6
// speedup vs baseline: 1.8289x; 1.0631x over previous
#include <cuda_runtime.h>
#include <cuda_bf16.h>
#include <math.h>

#define NB 4
#define NN 2048
#define PIN 256
#define POUT 128
#define FIN 512
#define FOUT 128
#define KH 32

typedef unsigned long long ull;

// ---------------- scratch (device globals) ----------------
__device__ float g_x [2][NB][NN][POUT];
__device__ float g_xh[2][NB][NN][POUT];
__device__ float g_s1[2][NB][NN][4];
__device__ float g_s2[2][NB][NN][4];
__device__ float g_G [2][NB][NN][POUT];
__device__ float g_h [2][NB][FOUT];
__device__ float g_gaga[2][NB][FOUT];

// ---------------- f32x2 helpers ----------------
__device__ __forceinline__ ull ffma2(ull a, ull b, ull c) {
    ull d; asm("fma.rn.f32x2 %0, %1, %2, %3;" : "=l"(d) : "l"(a), "l"(b), "l"(c)); return d;
}
__device__ __forceinline__ ull pack2(float v) {
    ull r; asm("mov.b64 %0, {%1, %1};" : "=l"(r) : "f"(v)); return r;
}
__device__ __forceinline__ ull packpair(float a, float b) {
    ull r; asm("mov.b64 %0, {%1, %2};" : "=l"(r) : "f"(a), "f"(b)); return r;
}
__device__ __forceinline__ float2 unpack2(ull v) {
    float2 r; asm("mov.b64 {%0, %1}, %2;" : "=f"(r.x), "=f"(r.y) : "l"(v)); return r;
}

// ---------------- GEMM: C[M,128] = A[M,KC] @ W[128,KC]^T + bias ----------------
template<int KC>
__device__ __forceinline__ void gemm_body(const float* __restrict__ A,
                                          const float* __restrict__ W,
                                          const float* __restrict__ bias,
                                          float* __restrict__ C)
{
    __shared__ float As[32][72];
    __shared__ float Ws[32][132];
    int t = threadIdx.x;
    int r0 = blockIdx.x * 64;
    int rr = (t >> 5) * 8;
    int cc = (t & 31) * 4;

    ull acc[4][4];
#pragma unroll
    for (int j = 0; j < 4; ++j)
#pragma unroll
        for (int c = 0; c < 4; ++c) acc[j][c] = 0ull;

    for (int kt = 0; kt < KC; kt += 32) {
        __syncthreads();
#pragma unroll
        for (int q = 0; q < 2; ++q) {
            int idx = t + 256 * q;
            int row = idx >> 3, kq = (idx & 7) * 4;
            float4 v = *reinterpret_cast<const float4*>(&A[(size_t)(r0 + row) * KC + kt + kq]);
            As[kq][row] = v.x; As[kq + 1][row] = v.y; As[kq + 2][row] = v.z; As[kq + 3][row] = v.w;
        }
#pragma unroll
        for (int q = 0; q < 4; ++q) {
            int idx = t + 256 * q;
            int c = idx >> 3, kq = (idx & 7) * 4;
            float4 v = *reinterpret_cast<const float4*>(&W[(size_t)c * KC + kt + kq]);
            Ws[kq][c] = v.x; Ws[kq + 1][c] = v.y; Ws[kq + 2][c] = v.z; Ws[kq + 3][c] = v.w;
        }
        __syncthreads();
#pragma unroll
        for (int k = 0; k < 32; ++k) {
            const ulonglong2* ap = reinterpret_cast<const ulonglong2*>(&As[k][rr]);
            ulonglong2 a01 = ap[0], a23 = ap[1];
            float4 w4 = *reinterpret_cast<const float4*>(&Ws[k][cc]);
            ull w0 = pack2(w4.x), w1 = pack2(w4.y), w2 = pack2(w4.z), w3 = pack2(w4.w);
            acc[0][0]=ffma2(a01.x,w0,acc[0][0]); acc[0][1]=ffma2(a01.x,w1,acc[0][1]);
            acc[0][2]=ffma2(a01.x,w2,acc[0][2]); acc[0][3]=ffma2(a01.x,w3,acc[0][3]);
            acc[1][0]=ffma2(a01.y,w0,acc[1][0]); acc[1][1]=ffma2(a01.y,w1,acc[1][1]);
            acc[1][2]=ffma2(a01.y,w2,acc[1][2]); acc[1][3]=ffma2(a01.y,w3,acc[1][3]);
            acc[2][0]=ffma2(a23.x,w0,acc[2][0]); acc[2][1]=ffma2(a23.x,w1,acc[2][1]);
            acc[2][2]=ffma2(a23.x,w2,acc[2][2]); acc[2][3]=ffma2(a23.x,w3,acc[2][3]);
            acc[3][0]=ffma2(a23.y,w0,acc[3][0]); acc[3][1]=ffma2(a23.y,w1,acc[3][1]);
            acc[3][2]=ffma2(a23.y,w2,acc[3][2]); acc[3][3]=ffma2(a23.y,w3,acc[3][3]);
        }
    }
    float b0=0.f,b1=0.f,b2=0.f,b3=0.f;
    if (bias) { b0=bias[cc]; b1=bias[cc+1]; b2=bias[cc+2]; b3=bias[cc+3]; }
#pragma unroll
    for (int j = 0; j < 4; ++j) {
        float2 v0=unpack2(acc[j][0]), v1=unpack2(acc[j][1]), v2=unpack2(acc[j][2]), v3=unpack2(acc[j][3]);
        int rowA = r0 + rr + j * 2;
        float4 oA = make_float4(v0.x+b0, v1.x+b1, v2.x+b2, v3.x+b3);
        float4 oB = make_float4(v0.y+b0, v1.y+b1, v2.y+b2, v3.y+b3);
        *reinterpret_cast<float4*>(&C[(size_t)rowA * 128 + cc]) = oA;
        *reinterpret_cast<float4*>(&C[(size_t)(rowA + 1) * 128 + cc]) = oB;
    }
}

__global__ __launch_bounds__(256)
void gemm_init_kernel(const float* __restrict__ bio_a, const float* __restrict__ bio_b,
                      const float* __restrict__ W, const float* __restrict__ bias)
{
    gemm_body<PIN>(blockIdx.z ? bio_b : bio_a, W, bias,
                   blockIdx.z ? &g_x[1][0][0][0] : &g_x[0][0][0][0]);
}
__global__ __launch_bounds__(256)
void gemm_proj_kernel(const float* __restrict__ W)
{
    gemm_body<POUT>(blockIdx.z ? &g_x[1][0][0][0] : &g_x[0][0][0][0], W, nullptr,
                    blockIdx.z ? &g_xh[1][0][0][0] : &g_xh[0][0][0][0]);
}

// ---------------- per-node attention scalars ----------------
__global__ void s_kernel(const float* __restrict__ attw)
{
    int g = blockIdx.x * blockDim.x + threadIdx.x;
    if (g >= 2 * NB * NN) return;
    int br = g / (NB * NN);
    int rem = g - br * NB * NN;
    int b = rem / NN, i = rem - b * NN;
    const float* xr = &g_xh[br][b][i][0];
    float s1o[4], s2o[4];
#pragma unroll
    for (int h = 0; h < 4; ++h) {
        float s1 = 0.f, s2 = 0.f;
#pragma unroll
        for (int k = 0; k < KH; k += 4) {
            float4 xv = *reinterpret_cast<const float4*>(&xr[h * KH + k]);
            float4 w1 = *reinterpret_cast<const float4*>(&attw[h * 64 + k]);
            float4 w2 = *reinterpret_cast<const float4*>(&attw[h * 64 + KH + k]);
            s1 += xv.x*w1.x + xv.y*w1.y + xv.z*w1.z + xv.w*w1.w;
            s2 += xv.x*w2.x + xv.y*w2.y + xv.z*w2.z + xv.w*w2.w;
        }
        s1o[h] = s1; s2o[h] = s2;
    }
    *reinterpret_cast<float4*>(&g_s1[br][b][i][0]) = make_float4(s1o[0],s1o[1],s1o[2],s1o[3]);
    *reinterpret_cast<float4*>(&g_s2[br][b][i][0]) = make_float4(s2o[0],s2o[1],s2o[2],s2o[3]);
}

// ---------------- fused GAT attention ----------------
// BI=64 rows/block, TJ=32 j-tile, 4 rows x 8 dims per thread.
// Pipeline: adjacency bitmask built once per block (prologue);
// xh tile register-double-buffered (LDG issued one tile ahead);
// only s2 LDGs remain in fill (8-deep MLP).
#define BI 64
#define TJ 32
#define WH  68
#define WJJ 272                    // 4 heads * 68
#define ADJS 65                    // adjbits row stride (words)
#define SM_W  (TJ * 128)           // 4096 floats: xh_s size
#define SM_ADJ (SM_W + TJ * WJJ)   // + 8704 floats: w_s size
#define ATTN_SMEM ((SM_ADJ + 64 * ADJS) * 4)   // 67,840 B

__global__ __launch_bounds__(256, 2)
void attn_kernel(const int* __restrict__ adjA, const int* __restrict__ adjB,
                 const float* __restrict__ attb)
{
    extern __shared__ float sm[];
    float* xh_s = sm;                                  // [TJ][128] permuted
    float* w_s  = sm + SM_W;                           // [TJ][WJJ]
    unsigned* adjbits = reinterpret_cast<unsigned*>(sm + SM_ADJ);

    int br = blockIdx.z, b = blockIdx.y;
    int i0 = blockIdx.x * BI;
    const int* adj = (br ? adjB : adjA) + (size_t)b * NN * NN;
    const float4* xh4 = reinterpret_cast<const float4*>(&g_xh[br][b][0][0]);
    int t = threadIdx.x, lane = t & 31, w = t >> 5;

    // ---- prologue: full adjacency bitmask for this block's 64 rows ----
    {
        int i = t >> 2, qd = t & 3;
        const int4* src = reinterpret_cast<const int4*>(adj + (size_t)(i0 + i) * NN + qd * 512);
#pragma unroll
        for (int wd = 0; wd < 16; ++wd) {
            unsigned bits = 0;
#pragma unroll
            for (int c = 0; c < 8; ++c) {
                int4 v = src[wd * 8 + c];
                bits |= (unsigned)(v.x != 0) << (c * 4)
                      | (unsigned)(v.y != 0) << (c * 4 + 1)
                      | (unsigned)(v.z != 0) << (c * 4 + 2)
                      | (unsigned)(v.w != 0) << (c * 4 + 3);
            }
            adjbits[i * ADJS + qd * 16 + wd] = bits;
        }
    }

    // fill-phase mapping: fixed row per thread, jj sweeps
    int p1_i = lane + 32 * (w & 1);
    int p1_jb = w >> 1;                                // jj = p1_jb + 4q, q<8
    float4 ab  = *reinterpret_cast<const float4*>(attb);
    float4 s1v = *reinterpret_cast<const float4*>(&g_s1[br][b][i0 + p1_i][0]);
    s1v.x += ab.x; s1v.y += ab.y; s1v.z += ab.z; s1v.w += ab.w;

    // main-phase mapping
    int ib  = t >> 4;                                  // rows 4ib..4ib+3
    int d0  = (t & 15) * 8;
    int h   = (t & 15) >> 2;
    int d0h = (t & 15) * 4;

    ull one2 = pack2(1.0f);
    ull acc[16];
#pragma unroll
    for (int q = 0; q < 16; ++q) acc[q] = 0ull;
    ull z01 = 0ull, z23 = 0ull;

    // xh tile prefetch mapping: dest float4 slot d -> src slot 2*(d&15)+(d>>4)
    int pf_row = lane;                  // one row per lane (warp covers 32 rows? no:)
    // thread q-th element: f = t + 256*q; row = f>>5 (0..31), dest slot = f&31
    float4 r0, r1, r2, r3;
    {
        int f0 = t, f1 = t + 256, f2 = t + 512, f3 = t + 768;
        int dd = t & 31; int ss = 2 * (dd & 15) + (dd >> 4);
        r0 = xh4[(size_t)(f0 >> 5) * 32 + ss];
        r1 = xh4[(size_t)(32 + (f1 >> 5) - 8) * 32 + ss]; // placeholder fixed below
        // recompute cleanly:
        r0 = xh4[(size_t)((f0 >> 5)) * 32 + ss];
        r1 = xh4[(size_t)((f1 >> 5)) * 32 + ss];
        r2 = xh4[(size_t)((f2 >> 5)) * 32 + ss];
        r3 = xh4[(size_t)((f3 >> 5)) * 32 + ss];
    }
    (void)pf_row;

    for (int jt = 0; jt < NN / TJ; ++jt) {
        int j0 = jt * TJ;
        __syncthreads();   // w_s & xh_s free; (first iter: adjbits ready)

        // store current tile's xh (dest slots contiguous per warp -> conflict-free)
        {
            int dd = t & 31;
            reinterpret_cast<float4*>(xh_s)[(size_t)((t) >> 5) * 32 + dd]        = r0;
            reinterpret_cast<float4*>(xh_s)[(size_t)((t + 256) >> 5) * 32 + dd]  = r1;
            reinterpret_cast<float4*>(xh_s)[(size_t)((t + 512) >> 5) * 32 + dd]  = r2;
            reinterpret_cast<float4*>(xh_s)[(size_t)((t + 768) >> 5) * 32 + dd]  = r3;
        }
        // prefetch next tile (latency hidden by fill + main)
        if (jt + 1 < NN / TJ) {
            int dd = t & 31; int ss = 2 * (dd & 15) + (dd >> 4);
            size_t base = (size_t)(j0 + TJ) * 32;
            r0 = xh4[base + (size_t)((t) >> 5) * 32 + ss];
            r1 = xh4[base + (size_t)((t + 256) >> 5) * 32 + ss];
            r2 = xh4[base + (size_t)((t + 512) >> 5) * 32 + ss];
            r3 = xh4[base + (size_t)((t + 768) >> 5) * 32 + ss];
        }

        // fill: adjacency from smem word, s2 from L2 (8-deep MLP)
        {
            unsigned bits = adjbits[p1_i * ADJS + jt];
            const float4* s2b = reinterpret_cast<const float4*>(&g_s2[br][b][j0][0]);
#pragma unroll
            for (int q = 0; q < 8; ++q) {
                int jj = p1_jb + 4 * q;
                float w0 = 0.f, w1 = 0.f, w2 = 0.f, w3 = 0.f;
                if ((bits >> jj) & 1u) {
                    float4 s2v = s2b[jj];
                    float t0 = s1v.x + s2v.x, t1 = s1v.y + s2v.y;
                    float t2 = s1v.z + s2v.z, t3 = s1v.w + s2v.w;
                    w0 = __expf(t0 >= 0.f ? t0 : 0.2f * t0);
                    w1 = __expf(t1 >= 0.f ? t1 : 0.2f * t1);
                    w2 = __expf(t2 >= 0.f ? t2 : 0.2f * t2);
                    w3 = __expf(t3 >= 0.f ? t3 : 0.2f * t3);
                }
                float* wr = &w_s[jj * WJJ + p1_i];
                wr[0 * WH] = w0; wr[1 * WH] = w1; wr[2 * WH] = w2; wr[3 * WH] = w3;
            }
        }
        __syncthreads();

        // main accumulate
#pragma unroll 4
        for (int jj = 0; jj < TJ; ++jj) {
            float4 wq = *reinterpret_cast<const float4*>(&w_s[jj * WJJ + h * WH + ib * 4]);
            const float* xrow = &xh_s[jj * 128];
            ulonglong2 xlo = *reinterpret_cast<const ulonglong2*>(xrow + d0h);
            ulonglong2 xhi = *reinterpret_cast<const ulonglong2*>(xrow + 64 + d0h);
            ull wp0 = pack2(wq.x), wp1 = pack2(wq.y), wp2 = pack2(wq.z), wp3 = pack2(wq.w);
            acc[0]  = ffma2(xlo.x, wp0, acc[0]);  acc[1]  = ffma2(xlo.y, wp0, acc[1]);
            acc[2]  = ffma2(xhi.x, wp0, acc[2]);  acc[3]  = ffma2(xhi.y, wp0, acc[3]);
            acc[4]  = ffma2(xlo.x, wp1, acc[4]);  acc[5]  = ffma2(xlo.y, wp1, acc[5]);
            acc[6]  = ffma2(xhi.x, wp1, acc[6]);  acc[7]  = ffma2(xhi.y, wp1, acc[7]);
            acc[8]  = ffma2(xlo.x, wp2, acc[8]);  acc[9]  = ffma2(xlo.y, wp2, acc[9]);
            acc[10] = ffma2(xhi.x, wp2, acc[10]); acc[11] = ffma2(xhi.y, wp2, acc[11]);
            acc[12] = ffma2(xlo.x, wp3, acc[12]); acc[13] = ffma2(xlo.y, wp3, acc[13]);
            acc[14] = ffma2(xhi.x, wp3, acc[14]); acc[15] = ffma2(xhi.y, wp3, acc[15]);
            z01 = ffma2(packpair(wq.x, wq.y), one2, z01);
            z23 = ffma2(packpair(wq.z, wq.w), one2, z23);
        }
    }

    float2 za = unpack2(z01), zb = unpack2(z23);
    float zs[4] = { za.x, za.y, zb.x, zb.y };
#pragma unroll
    for (int r = 0; r < 4; ++r) {
        int row = i0 + ib * 4 + r;
        float z = zs[r];
        float inv = 1.0f / ((z == 0.f) ? 1.f : z);
        float2 v0 = unpack2(acc[r*4+0]);
        float2 v1 = unpack2(acc[r*4+1]);
        float2 v2 = unpack2(acc[r*4+2]);
        float2 v3 = unpack2(acc[r*4+3]);
        float4 x0 = *reinterpret_cast<const float4*>(&g_x[br][b][row][d0]);
        float4 x1 = *reinterpret_cast<const float4*>(&g_x[br][b][row][d0 + 4]);
        float4 o0, o1;
        o0.x = fmaxf(v0.x*inv,0.f)+x0.x; o0.y = fmaxf(v0.y*inv,0.f)+x0.y;
        o0.z = fmaxf(v1.x*inv,0.f)+x0.z; o0.w = fmaxf(v1.y*inv,0.f)+x0.w;
        o1.x = fmaxf(v2.x*inv,0.f)+x1.x; o1.y = fmaxf(v2.y*inv,0.f)+x1.y;
        o1.z = fmaxf(v3.x*inv,0.f)+x1.z; o1.w = fmaxf(v3.y*inv,0.f)+x1.w;
        *reinterpret_cast<float4*>(&g_G[br][b][row][d0])     = o0;
        *reinterpret_cast<float4*>(&g_G[br][b][row][d0 + 4]) = o1;
    }
}

// ---------------- GGE MLP ----------------
__global__ __launch_bounds__(512)
void gge_kernel(const float* __restrict__ a_in, const float* __restrict__ b_in,
                const float* __restrict__ W1, const float* __restrict__ b1,
                const float* __restrict__ W2, const float* __restrict__ b2)
{
    int br = blockIdx.x, bb = blockIdx.y;
    const float* in = (br ? b_in : a_in) + (size_t)bb * FIN;
    __shared__ float a_s[FIN];
    __shared__ float part[4][128];
    __shared__ float h1[128];
    int t = threadIdx.x;
    if (t < FIN) a_s[t] = in[t];
    __syncthreads();
    int d = t & 127, g = t >> 7;
    float acc = 0.f;
    for (int k = g * 128; k < g * 128 + 128; k += 4) {
        float4 w = *reinterpret_cast<const float4*>(&W1[(size_t)d * FIN + k]);
        acc += a_s[k]*w.x + a_s[k+1]*w.y + a_s[k+2]*w.z + a_s[k+3]*w.w;
    }
    part[g][d] = acc;
    __syncthreads();
    if (t < 128) h1[t] = fmaxf(part[0][t]+part[1][t]+part[2][t]+part[3][t] + b1[t], 0.f);
    __syncthreads();
    float acc2 = 0.f;
    for (int k = g * 32; k < g * 32 + 32; k += 4) {
        float4 w = *reinterpret_cast<const float4*>(&W2[(size_t)d * 128 + k]);
        acc2 += h1[k]*w.x + h1[k+1]*w.y + h1[k+2]*w.z + h1[k+3]*w.w;
    }
    part[g][d] = acc2;
    __syncthreads();
    if (t < 128) g_h[br][bb][t] = fmaxf(part[0][t]+part[1][t]+part[2][t]+part[3][t] + b2[t], 0.f);
}

// ---------------- GAGA pooling (1024 threads) ----------------
__global__ __launch_bounds__(1024)
void gaga_kernel()
{
    int b = blockIdx.x, br = blockIdx.y;
    const float* G = &g_G[br][b][0][0];
    __shared__ float h_s[128];
    __shared__ float p_s[NN];
    __shared__ float red1[32], red2[32];
    __shared__ float partial[8][128];
    int t = threadIdx.x, lane = t & 31, w = t >> 5;

    if (t < 128) h_s[t] = g_h[br][b][t];
    __syncthreads();

    for (int n = w * 64; n < w * 64 + 64; ++n) {
        float4 gv = *reinterpret_cast<const float4*>(&G[(size_t)n * 128 + lane * 4]);
        float4 hv = *reinterpret_cast<const float4*>(&h_s[lane * 4]);
        float v = gv.x*hv.x + gv.y*hv.y + gv.z*hv.z + gv.w*hv.w;
#pragma unroll
        for (int s = 16; s > 0; s >>= 1) v += __shfl_xor_sync(0xffffffffu, v, s);
        if (lane == 0) p_s[n] = v;
    }
    __syncthreads();

    float m = fmaxf(p_s[t], p_s[t + 1024]);
#pragma unroll
    for (int s = 16; s > 0; s >>= 1) m = fmaxf(m, __shfl_xor_sync(0xffffffffu, m, s));
    if (lane == 0) red1[w] = m;
    __syncthreads();
    if (w == 0) {
        float mm = red1[lane];
#pragma unroll
        for (int s = 16; s > 0; s >>= 1) mm = fmaxf(mm, __shfl_xor_sync(0xffffffffu, mm, s));
        if (lane == 0) red1[0] = mm;
    }
    __syncthreads();
    m = red1[0];

    float e0 = __expf(p_s[t] - m);
    float e1 = __expf(p_s[t + 1024] - m);
    p_s[t] = e0; p_s[t + 1024] = e1;
    float s = e0 + e1;
#pragma unroll
    for (int q = 16; q > 0; q >>= 1) s += __shfl_xor_sync(0xffffffffu, s, q);
    if (lane == 0) red2[w] = s;
    __syncthreads();
    if (w == 0) {
        float ss = red2[lane];
#pragma unroll
        for (int q = 16; q > 0; q >>= 1) ss += __shfl_xor_sync(0xffffffffu, ss, q);
        if (lane == 0) red2[0] = ss;
    }
    __syncthreads();
    float Z = red2[0];

    int d = t & 127, g = t >> 7;
    float acc = 0.f;
    for (int n = g * 256; n < g * 256 + 256; ++n)
        acc += p_s[n] * G[(size_t)n * 128 + d];
    partial[g][d] = acc;
    __syncthreads();
    if (t < 128) {
        float tot = 0.f;
#pragma unroll
        for (int q = 0; q < 8; ++q) tot += partial[q][t];
        g_gaga[br][b][t] = tot / Z;
    }
}

// ---------------- LED head + log_softmax (1024 threads) ----------------
__global__ __launch_bounds__(1024)
void led_kernel(const float* __restrict__ convW, const float* __restrict__ convb,
                const float* __restrict__ W1, const float* __restrict__ b1,
                const float* __restrict__ W2, const float* __restrict__ b2,
                float* __restrict__ out)
{
    __shared__ float ea[NB * 256], eb[NB * 256];
    __shared__ float feat[NB * 512];
    __shared__ float part2[2][NB * 128];
    __shared__ float x1[NB * 128];
    __shared__ float lg[NB * 2];
    int t = threadIdx.x;

    {
        int bb = t >> 8, d = t & 255;
        ea[t] = (d < 128) ? g_h[0][bb][d] : g_gaga[0][bb][d - 128];
        eb[t] = (d < 128) ? g_h[1][bb][d] : g_gaga[1][bb][d - 128];
    }
    __syncthreads();

    {
        int bb = t >> 8, o = t & 255;
        float sa = 0.f, sb = 0.f;
        for (int k = 0; k < 256; k += 4) {
            float4 w = *reinterpret_cast<const float4*>(&convW[(size_t)o * 256 + k]);
            sa += ea[bb*256+k]*w.x + ea[bb*256+k+1]*w.y + ea[bb*256+k+2]*w.z + ea[bb*256+k+3]*w.w;
            sb += eb[bb*256+k]*w.x + eb[bb*256+k+1]*w.y + eb[bb*256+k+2]*w.z + eb[bb*256+k+3]*w.w;
        }
        feat[bb * 512 + o]       = fmaxf(sa, sb) + convb[o];
        feat[bb * 512 + 256 + o] = ea[bb * 256 + o] - eb[bb * 256 + o];
    }
    __syncthreads();

    {
        int g = t >> 9, idx = t & 511;
        int bb = idx >> 7, d = idx & 127;
        float acc = 0.f;
        for (int k = g * 256; k < g * 256 + 256; k += 4) {
            float4 w = *reinterpret_cast<const float4*>(&W1[(size_t)d * 512 + k]);
            acc += feat[bb*512+k]*w.x + feat[bb*512+k+1]*w.y + feat[bb*512+k+2]*w.z + feat[bb*512+k+3]*w.w;
        }
        part2[g][idx] = acc;
    }
    __syncthreads();
    if (t < 512) {
        int d = t & 127;
        x1[t] = fmaxf(part2[0][t] + part2[1][t] + b1[d], 0.f);
    }
    __syncthreads();

    if (t < NB * 2) {
        int bb = t >> 1, c = t & 1;
        float acc = b2[c];
        for (int k = 0; k < 128; ++k) acc += x1[bb * 128 + k] * W2[c * 128 + k];
        lg[bb * 2 + c] = acc;
    }
    __syncthreads();
    if (t < NB) {
        float l0 = lg[t * 2], l1 = lg[t * 2 + 1];
        float m = fmaxf(l0, l1);
        float lse = m + logf(expf(l0 - m) + expf(l1 - m));
        out[t * 2]     = l0 - lse;
        out[t * 2 + 1] = l1 - lse;
    }
}

// ---------------- host ----------------
extern "C" void kernel_launch(void* const* d_in, const int* in_sizes, int n_in,
                              void* d_out, int out_size)
{
    const float* a      = (const float*)d_in[0];
    const float* bio_a  = (const float*)d_in[1];
    const int*   A      = (const int*)  d_in[2];
    const float* b      = (const float*)d_in[3];
    const float* bio_b  = (const float*)d_in[4];
    const int*   B      = (const int*)  d_in[5];
    const float* initW  = (const float*)d_in[6];
    const float* initb  = (const float*)d_in[7];
    const float* projW  = (const float*)d_in[8];
    const float* attw   = (const float*)d_in[9];
    const float* attb   = (const float*)d_in[10];
    const float* ggeW1  = (const float*)d_in[11];
    const float* ggeb1  = (const float*)d_in[12];
    const float* ggeW2  = (const float*)d_in[13];
    const float* ggeb2  = (const float*)d_in[14];
    const float* convW  = (const float*)d_in[15];
    const float* convb  = (const float*)d_in[16];
    const float* ledW1  = (const float*)d_in[17];
    const float* ledb1  = (const float*)d_in[18];
    const float* ledW2  = (const float*)d_in[19];
    const float* ledb2  = (const float*)d_in[20];
    float* out = (float*)d_out;

    cudaFuncSetAttribute(attn_kernel, cudaFuncAttributeMaxDynamicSharedMemorySize, ATTN_SMEM);

    dim3 gGemm(NB * NN / 64, 1, 2);
    gemm_init_kernel<<<gGemm, 256>>>(bio_a, bio_b, initW, initb);
    gemm_proj_kernel<<<gGemm, 256>>>(projW);
    s_kernel<<<(2 * NB * NN + 255) / 256, 256>>>(attw);

    dim3 gAttn(NN / BI, NB, 2);
    attn_kernel<<<gAttn, 256, ATTN_SMEM>>>(A, B, attb);

    dim3 gGge(2, NB);
    gge_kernel<<<gGge, 512>>>(a, b, ggeW1, ggeb1, ggeW2, ggeb2);

    dim3 gGaga(NB, 2);
    gaga_kernel<<<gGaga, 1024>>>();

    led_kernel<<<1, 1024>>>(convW, convb, ledW1, ledb1, ledW2, ledb2, out);
}